// round 5
// baseline (speedup 1.0000x reference)
#include <cuda_runtime.h>

#define B_TOTAL 32768
#define NNODES  16
#define NDIM    64
#define HID     128
#define NC      10
#define G       4
#define THREADS 256
#define HPAD    132                 // hg row stride
#define QPAD    144                 // q/k/v row stride; head h at offset 36h

// shared memory layout (float offsets)
#define OFF_WB0   0                 // 8192 fl = 32KB weight chunk buffer 0
#define OFF_WB1   8192              // buffer 1
#define OFF_BIAS  16384
#define   B_ENC   0
#define   B_BQ    128               // +128*l
#define   B_BK    384
#define   B_BV    640
#define   B_LNG   896
#define   B_LNB   1152
#define   B_B1    1408
#define   B_B2    1536
#define OFF_MBAR  17984             // 2 mbarriers (16 B), 16B-aligned
#define OFF_DATA  18048
#define GFL       (16*HPAD + 3*16*QPAD)     // 2112 + 6912 = 9024 per graph
#define SMEM_FLOATS (OFF_DATA + G*GFL)      // 54144
#define SMEM_BYTES  (SMEM_FLOATS*4)         // 216576
#define MBAR_B    (OFF_MBAR*4)

typedef unsigned long long ull;

__device__ __forceinline__ ull pack2(float x, float y) {
    ull r; asm("mov.b64 %0, {%1,%2};" : "=l"(r) : "f"(x), "f"(y)); return r;
}
__device__ __forceinline__ float2 unpack2(ull v) {
    float2 r; asm("mov.b64 {%0,%1}, %2;" : "=f"(r.x), "=f"(r.y) : "l"(v)); return r;
}
__device__ __forceinline__ void fma2(ull& d, ull a, ull b) {
    asm("fma.rn.f32x2 %0, %1, %2, %0;" : "+l"(d) : "l"(a), "l"(b));
}
__device__ __forceinline__ unsigned su32(const void* p) {
    return (unsigned)__cvta_generic_to_shared(p);
}
__device__ __forceinline__ void mbar_init(unsigned a, unsigned cnt) {
    asm volatile("mbarrier.init.shared.b64 [%0], %1;" :: "r"(a), "r"(cnt) : "memory");
}
__device__ __forceinline__ void mbw(unsigned a, unsigned parity) {
    asm volatile("{\n\t.reg .pred P;\nWAIT%=:\n\t"
        "mbarrier.try_wait.parity.acquire.cta.shared::cta.b64 P, [%0], %1, 0x989680;\n\t"
        "@!P bra WAIT%=;\n\t}" :: "r"(a), "r"(parity) : "memory");
}
__device__ __forceinline__ void bulk_issue(unsigned dst, const float* src,
                                           unsigned bytes, unsigned mbar) {
    asm volatile("mbarrier.arrive.expect_tx.shared::cta.b64 _, [%0], %1;"
                 :: "r"(mbar), "r"(bytes) : "memory");
    asm volatile("cp.async.bulk.shared::cluster.global.mbarrier::complete_tx::bytes "
                 "[%0], [%1], %2, [%3];"
                 :: "r"(dst), "l"(src), "r"(bytes), "r"(mbar) : "memory");
}

// k-paired gemm over a 64-row weight chunk.
// acc[4n+j] is an f32x2 holding (even-k partial, odd-k partial) for node n0+n,
// column c+j. h pairs (k,k+1) load directly as aligned 64-bit — zero MOVs.
template<int INSTRIDE>
__device__ __forceinline__ void gemm64(const float* __restrict__ in,
                                       const float* __restrict__ Wc,
                                       int c, ull* __restrict__ acc)
{
#pragma unroll 2
    for (int k0 = 0; k0 < 64; k0 += 4) {
        float4 w0 = *(const float4*)(Wc + (k0    )*HID + c);
        float4 w1 = *(const float4*)(Wc + (k0 + 1)*HID + c);
        float4 w2 = *(const float4*)(Wc + (k0 + 2)*HID + c);
        float4 w3 = *(const float4*)(Wc + (k0 + 3)*HID + c);
        ull wp0 = pack2(w0.x, w1.x), wp1 = pack2(w0.y, w1.y);
        ull wp2 = pack2(w0.z, w1.z), wp3 = pack2(w0.w, w1.w);
        ull wq0 = pack2(w2.x, w3.x), wq1 = pack2(w2.y, w3.y);
        ull wq2 = pack2(w2.z, w3.z), wq3 = pack2(w2.w, w3.w);
#pragma unroll
        for (int n = 0; n < 8; n++) {
            double2 hv = *(const double2*)(in + n*INSTRIDE + k0);
            ull h01 = __double_as_longlong(hv.x);
            ull h23 = __double_as_longlong(hv.y);
            ull* a = acc + 4*n;
            fma2(a[0], h01, wp0); fma2(a[1], h01, wp1);
            fma2(a[2], h01, wp2); fma2(a[3], h01, wp3);
            fma2(a[0], h23, wq0); fma2(a[1], h23, wq1);
            fma2(a[2], h23, wq2); fma2(a[3], h23, wq3);
        }
    }
}

__device__ __forceinline__ void acc_init(ull* acc, const float* __restrict__ bp, int c) {
    ull b0 = pack2(bp[c],   0.f), b1 = pack2(bp[c+1], 0.f);
    ull b2 = pack2(bp[c+2], 0.f), b3 = pack2(bp[c+3], 0.f);
#pragma unroll
    for (int n = 0; n < 8; n++) {
        acc[4*n] = b0; acc[4*n+1] = b1; acc[4*n+2] = b2; acc[4*n+3] = b3;
    }
}

// reduce (even,odd) halves and store 4 cols
template<int OPAD>
__device__ __forceinline__ void store_acc(float* __restrict__ out, int n0, int off,
                                          const ull* __restrict__ acc)
{
#pragma unroll
    for (int n = 0; n < 8; n++) {
        const ull* a = acc + 4*n;
        float2 s0 = unpack2(a[0]), s1 = unpack2(a[1]);
        float2 s2 = unpack2(a[2]), s3 = unpack2(a[3]);
        *(float4*)(out + (n0 + n)*OPAD + off) =
            make_float4(s0.x + s0.y, s1.x + s1.y, s2.x + s2.y, s3.x + s3.y);
    }
}

__global__ void __launch_bounds__(THREADS, 1)
gnn_fused_kernel(const float* __restrict__ x,
                 const float* __restrict__ enc_W, const float* __restrict__ enc_b,
                 const float* __restrict__ Wq, const float* __restrict__ bq,
                 const float* __restrict__ Wk, const float* __restrict__ bk,
                 const float* __restrict__ Wv, const float* __restrict__ bv,
                 const float* __restrict__ ln_g, const float* __restrict__ ln_b,
                 const float* __restrict__ W1, const float* __restrict__ b1,
                 const float* __restrict__ W2, const float* __restrict__ b2,
                 float* __restrict__ out)
{
    extern __shared__ float sm[];
    const unsigned smb = su32(sm);
    float* bias = sm + OFF_BIAS;

    const int tid  = threadIdx.x;
    const int lane = tid & 31;
    const int warp = tid >> 5;
    const int gs   = warp >> 1;
    const int wsub = warp & 1;
    const int n0   = wsub * 8;
    const int c    = lane << 2;                       // my 4 output columns
    const int qoff = (c >> 5)*36 + (c & 31);          // head-padded offset

    float* hg = sm + OFF_DATA + gs*GFL;
    float* qg = hg + 16*HPAD;          // +2112
    float* kg = qg + 16*QPAD;          // +2304
    float* vg = kg + 16*QPAD;

    // ---- mbarriers + first two weight chunks ----
    if (tid == 0) {
        mbar_init(smb + MBAR_B,     1);
        mbar_init(smb + MBAR_B + 8, 1);
        asm volatile("fence.proxy.async.shared::cta;" ::: "memory");
        bulk_issue(smb + OFF_WB0*4, enc_W, 32768u, smb + MBAR_B);       // c0
        bulk_issue(smb + OFF_WB1*4, Wq,    32768u, smb + MBAR_B + 8);   // c1
    }

    // ---- preload biases / ln params ----
    for (int i = tid; i < 128; i += THREADS) {
        bias[B_ENC + i] = enc_b[i];
        bias[B_B1  + i] = b1[i];
    }
    for (int i = tid; i < 256; i += THREADS) {
        bias[B_BQ  + i] = bq[i];
        bias[B_BK  + i] = bk[i];
        bias[B_BV  + i] = bv[i];
        bias[B_LNG + i] = ln_g[i];
        bias[B_LNB + i] = ln_b[i];
    }
    if (tid < NC) bias[B_B2 + tid] = b2[tid];

    // ---- stage x (4 graphs x 1024 floats) into Q region, row stride 64 ----
    {
        const float4* xs = (const float4*)(x + (size_t)blockIdx.x * (G*NNODES*NDIM));
        float* xb = sm + OFF_DATA + 16*HPAD;     // qg of graph 0
        for (int i = tid; i < (G*NNODES*NDIM)/4; i += THREADS) {
            int g = i >> 8;              // 256 float4 per graph
            int r = i & 255;
            *(float4*)(xb + g*GFL + (r << 2)) = xs[i];
        }
    }
    __syncthreads();    // publish biases + x staging + mbarrier init

    int wc = 0;         // next chunk to consume
    int ic = 2;         // next chunk to issue
#define TWAIT() mbw(smb + MBAR_B + (wc & 1)*8, (wc >> 1) & 1)
#define TISSUE(src, bytes) do { if (tid == 0) \
        bulk_issue(smb + ((ic & 1) ? OFF_WB1 : OFF_WB0)*4, (src), (bytes), \
                   smb + MBAR_B + (ic & 1)*8); ic++; } while (0)

    ull acc[32];

    // ---- encode: h = x @ enc_W + enc_b  (K=64, one chunk) ----
    {
        TWAIT();                               // c0
        acc_init(acc, bias + B_ENC, c);
        gemm64<NDIM>(qg + n0*NDIM, sm + OFF_WB0, c, acc);
        store_acc<HPAD>(hg, n0, c, acc);
        __syncthreads();
        TISSUE(Wq + 8192, 32768u);             // c2: Wq[0] rows 64..127
        wc = 1;
    }

    const float scale = 0.1767766952966369f;   // 1/sqrt(32)

    for (int l = 0; l < 2; l++) {
        const float* nexts[6] = {
            Wk + l*16384, Wk + l*16384 + 8192,
            Wv + l*16384, Wv + l*16384 + 8192,
            (l == 0) ? (Wq + 16384) : W1,
            (l == 0) ? (Wq + 16384 + 8192) : (W1 + 8192)
        };
        const float* bptr[3] = { bias + B_BQ + 128*l, bias + B_BK + 128*l,
                                 bias + B_BV + 128*l };
        float* outs[3] = { qg, kg, vg };

#pragma unroll
        for (int s = 0; s < 3; s++) {
            TWAIT();
            acc_init(acc, bptr[s], c);
            gemm64<HPAD>(hg + n0*HPAD, sm + ((wc & 1) ? OFF_WB1 : OFF_WB0), c, acc);
            __syncthreads();
            TISSUE(nexts[2*s], 32768u);
            wc++;
            TWAIT();
            gemm64<HPAD>(hg + n0*HPAD + 64, sm + ((wc & 1) ? OFF_WB1 : OFF_WB0), c, acc);
            store_acc<QPAD>(outs[s], n0, qoff, acc);
            __syncthreads();
            TISSUE(nexts[2*s + 1], 32768u);
            wc++;
        }

        // ---- attention + residual + layernorm (registers; lane=(node,head)) ----
        {
            const int n  = n0 + (lane & 7);
            const int hh = lane >> 3;
            const int co = hh * 36;      // q/k/v head-padded offset
            const int ch = hh * 32;      // hg linear offset

            float q[32];
            const float* qr = qg + n*QPAD + co;
#pragma unroll
            for (int j = 0; j < 8; j++) {
                float4 t = *(const float4*)(qr + 4*j);
                q[4*j] = t.x; q[4*j+1] = t.y; q[4*j+2] = t.z; q[4*j+3] = t.w;
            }
            float s[16];
#pragma unroll
            for (int m = 0; m < 16; m++) {
                const float* kr = kg + m*QPAD + co;
                float a0 = 0.f, a1 = 0.f, a2 = 0.f, a3 = 0.f;
#pragma unroll
                for (int j = 0; j < 8; j++) {
                    float4 t = *(const float4*)(kr + 4*j);
                    a0 += q[4*j]  *t.x; a1 += q[4*j+1]*t.y;
                    a2 += q[4*j+2]*t.z; a3 += q[4*j+3]*t.w;
                }
                s[m] = (a0 + a1 + a2 + a3) * scale;
            }
            float mx = s[0];
#pragma unroll
            for (int m = 1; m < 16; m++) mx = fmaxf(mx, s[m]);
            float ssum = 0.f;
#pragma unroll
            for (int m = 0; m < 16; m++) { s[m] = __expf(s[m] - mx); ssum += s[m]; }
            float inv = 1.f / ssum;

            float o[32];
#pragma unroll
            for (int j = 0; j < 32; j++) o[j] = 0.f;
#pragma unroll
            for (int m = 0; m < 16; m++) {
                float p = s[m] * inv;
                const float* vr = vg + m*QPAD + co;
#pragma unroll
                for (int j = 0; j < 8; j++) {
                    float4 t = *(const float4*)(vr + 4*j);
                    o[4*j]   += p*t.x; o[4*j+1] += p*t.y;
                    o[4*j+2] += p*t.z; o[4*j+3] += p*t.w;
                }
            }
            // residual
            float* hr = hg + n*HPAD + ch;
#pragma unroll
            for (int j = 0; j < 8; j++) {
                float4 t = *(const float4*)(hr + 4*j);
                o[4*j] += t.x; o[4*j+1] += t.y; o[4*j+2] += t.z; o[4*j+3] += t.w;
            }
            // LN stats across the 4 head-lanes of this node
            float lsum = 0.f, lsq = 0.f;
#pragma unroll
            for (int j = 0; j < 32; j++) { lsum += o[j]; lsq += o[j]*o[j]; }
            lsum += __shfl_xor_sync(0xffffffffu, lsum, 8);
            lsq  += __shfl_xor_sync(0xffffffffu, lsq,  8);
            lsum += __shfl_xor_sync(0xffffffffu, lsum, 16);
            lsq  += __shfl_xor_sync(0xffffffffu, lsq,  16);
            float mean = lsum * (1.f/HID);
            float var  = lsq  * (1.f/HID) - mean*mean;
            float rstd = rsqrtf(var + 1e-5f);
#pragma unroll
            for (int j = 0; j < 32; j++)
                o[j] = (o[j] - mean) * rstd * bias[B_LNG + 128*l + ch + j]
                       + bias[B_LNB + 128*l + ch + j];
#pragma unroll
            for (int j = 0; j < 8; j++)
                *(float4*)(hr + 4*j) = make_float4(o[4*j], o[4*j+1], o[4*j+2], o[4*j+3]);
        }
        __syncthreads();
    }

    // ---- pooling into qg scratch: [0..128)=mean, [128..256)=max ----
    {
        int cA = wsub*64 + lane, cB = cA + 32;
        float sA = 0.f, sB = 0.f, mA = -3.4e38f, mB = -3.4e38f;
#pragma unroll
        for (int nn = 0; nn < 16; nn++) {
            float a = hg[nn*HPAD + cA]; sA += a; mA = fmaxf(mA, a);
            float b = hg[nn*HPAD + cB]; sB += b; mB = fmaxf(mB, b);
        }
        qg[cA]       = sA * (1.f/16.f);
        qg[HID + cA] = mA;
        qg[cB]       = sB * (1.f/16.f);
        qg[HID + cB] = mB;
    }
    __syncthreads();

    // ---- MLP layer 1: 4 chunks of W1 (256x128); c13,c14 already in flight ----
    {
        int cA = wsub*64 + lane, cB = cA + 32;
        float a1 = bias[B_B1 + cA];
        float a2 = bias[B_B1 + cB];
        for (int cc = 0; cc < 4; cc++) {
            TWAIT();
            float* bufp = sm + ((wc & 1) ? OFF_WB1 : OFF_WB0);
#pragma unroll 8
            for (int k = 0; k < 64; k++) {
                float pv = qg[64*cc + k];
                a1 = fmaf(pv, bufp[k*HID + cA], a1);
                a2 = fmaf(pv, bufp[k*HID + cB], a2);
            }
            __syncthreads();
            if (cc < 3) {
                const float* src = (cc < 2) ? (W1 + (cc + 2)*8192) : W2;
                unsigned nb = (cc < 2) ? 32768u : 5120u;   // W2 = 128*10 fl = 5120 B
                TISSUE(src, nb);
            }
            wc++;
        }
        kg[cA] = fmaxf(a1, 0.f);
        kg[cB] = fmaxf(a2, 0.f);
    }
    __syncthreads();

    // ---- logits = hid @ W2 + b2 ----
    TWAIT();    // c17
    {
        const float* Wc = sm + ((wc & 1) ? OFF_WB1 : OFF_WB0);
        if (wsub == 0 && lane < NC) {
            float a = bias[B_B2 + lane];
#pragma unroll 8
            for (int k = 0; k < HID; k++)
                a = fmaf(kg[k], Wc[k*NC + lane], a);
            out[((size_t)blockIdx.x*G + gs)*NC + lane] = a;
        }
    }
#undef TWAIT
#undef TISSUE
}

extern "C" void kernel_launch(void* const* d_in, const int* in_sizes, int n_in,
                              void* d_out, int out_size)
{
    const float* x     = (const float*)d_in[0];
    const float* enc_W = (const float*)d_in[1];
    const float* enc_b = (const float*)d_in[2];
    const float* Wq    = (const float*)d_in[3];
    const float* bq    = (const float*)d_in[4];
    const float* Wk    = (const float*)d_in[5];
    const float* bk    = (const float*)d_in[6];
    const float* Wv    = (const float*)d_in[7];
    const float* bv    = (const float*)d_in[8];
    const float* ln_g  = (const float*)d_in[9];
    const float* ln_b  = (const float*)d_in[10];
    const float* W1    = (const float*)d_in[11];
    const float* b1    = (const float*)d_in[12];
    const float* W2    = (const float*)d_in[13];
    const float* b2    = (const float*)d_in[14];
    float* out = (float*)d_out;

    cudaFuncSetAttribute(gnn_fused_kernel,
                         cudaFuncAttributeMaxDynamicSharedMemorySize, SMEM_BYTES);

    gnn_fused_kernel<<<B_TOTAL / G, THREADS, SMEM_BYTES>>>(
        x, enc_W, enc_b, Wq, bq, Wk, bk, Wv, bv, ln_g, ln_b, W1, b1, W2, b2, out);
}

// round 6
// speedup vs baseline: 1.4862x; 1.4862x over previous
#include <cuda_runtime.h>

#define B_TOTAL 32768
#define NNODES  16
#define NDIM    64
#define HID     128
#define NC      10
#define G       4
#define THREADS 256
#define HPAD    132                 // hg row stride
#define QPAD    144                 // q/k/v row stride; head h at offset 36h

// shared memory layout (float offsets)
#define OFF_WB0   0                 // 8192 fl = 32KB weight chunk buffer 0
#define OFF_WB1   8192              // buffer 1
#define OFF_BIAS  16384
#define   B_ENC   0
#define   B_BQ    128               // +128*l
#define   B_BK    384
#define   B_BV    640
#define   B_LNG   896
#define   B_LNB   1152
#define   B_B1    1408
#define   B_B2    1536
#define OFF_MBAR  17984             // 2 mbarriers (16 B), 16B-aligned
#define OFF_DATA  18048
#define GFL       (16*HPAD + 3*16*QPAD)     // 2112 + 6912 = 9024 per graph
#define SMEM_FLOATS (OFF_DATA + G*GFL)      // 54144
#define SMEM_BYTES  (SMEM_FLOATS*4)         // 216576
#define MBAR_B    (OFF_MBAR*4)

typedef unsigned long long ull;

__device__ __forceinline__ ull pack2(float x, float y) {
    ull r; asm("mov.b64 %0, {%1,%2};" : "=l"(r) : "f"(x), "f"(y)); return r;
}
__device__ __forceinline__ float2 unpack2(ull v) {
    float2 r; asm("mov.b64 {%0,%1}, %2;" : "=f"(r.x), "=f"(r.y) : "l"(v)); return r;
}
__device__ __forceinline__ void fma2(ull& d, ull a, ull b) {
    asm("fma.rn.f32x2 %0, %1, %2, %0;" : "+l"(d) : "l"(a), "l"(b));
}
__device__ __forceinline__ unsigned su32(const void* p) {
    return (unsigned)__cvta_generic_to_shared(p);
}
__device__ __forceinline__ void mbar_init(unsigned a, unsigned cnt) {
    asm volatile("mbarrier.init.shared.b64 [%0], %1;" :: "r"(a), "r"(cnt) : "memory");
}
__device__ __forceinline__ void mbw(unsigned a, unsigned parity) {
    asm volatile("{\n\t.reg .pred P;\nWAIT%=:\n\t"
        "mbarrier.try_wait.parity.acquire.cta.shared::cta.b64 P, [%0], %1, 0x989680;\n\t"
        "@!P bra WAIT%=;\n\t}" :: "r"(a), "r"(parity) : "memory");
}
__device__ __forceinline__ void bulk_issue(unsigned dst, const float* src,
                                           unsigned bytes, unsigned mbar) {
    asm volatile("mbarrier.arrive.expect_tx.shared::cta.b64 _, [%0], %1;"
                 :: "r"(mbar), "r"(bytes) : "memory");
    asm volatile("cp.async.bulk.shared::cluster.global.mbarrier::complete_tx::bytes "
                 "[%0], [%1], %2, [%3];"
                 :: "r"(dst), "l"(src), "r"(bytes), "r"(mbar) : "memory");
}

// R4 column-paired gemm over a 64-row weight chunk.
// Lane owns 4 contiguous output cols c..c+3; accA=(c,c+1), accB=(c+2,c+3).
// W packs are register-consecutive (free); h dup-packs lower to fma-pipe MOVs.
template<int INSTRIDE>
__device__ __forceinline__ void gemm64(const float* __restrict__ in,
                                       const float* __restrict__ Wc,
                                       int c, ull* accA, ull* accB)
{
#pragma unroll 2
    for (int k0 = 0; k0 < 64; k0 += 4) {
        float4 w0 = *(const float4*)(Wc + (k0    )*HID + c);
        float4 w1 = *(const float4*)(Wc + (k0 + 1)*HID + c);
        float4 w2 = *(const float4*)(Wc + (k0 + 2)*HID + c);
        float4 w3 = *(const float4*)(Wc + (k0 + 3)*HID + c);
        ull w0A = pack2(w0.x, w0.y), w0B = pack2(w0.z, w0.w);
        ull w1A = pack2(w1.x, w1.y), w1B = pack2(w1.z, w1.w);
        ull w2A = pack2(w2.x, w2.y), w2B = pack2(w2.z, w2.w);
        ull w3A = pack2(w3.x, w3.y), w3B = pack2(w3.z, w3.w);
#pragma unroll
        for (int n = 0; n < 8; n++) {
            float4 hv = *(const float4*)(in + n*INSTRIDE + k0);
            ull h0 = pack2(hv.x, hv.x), h1 = pack2(hv.y, hv.y);
            ull h2 = pack2(hv.z, hv.z), h3 = pack2(hv.w, hv.w);
            fma2(accA[n], h0, w0A); fma2(accB[n], h0, w0B);
            fma2(accA[n], h1, w1A); fma2(accB[n], h1, w1B);
            fma2(accA[n], h2, w2A); fma2(accB[n], h2, w2B);
            fma2(accA[n], h3, w3A); fma2(accB[n], h3, w3B);
        }
    }
}

__device__ __forceinline__ void acc_init(ull* accA, ull* accB,
                                         const float* __restrict__ bp, int c) {
    ull bA = pack2(bp[c],     bp[c + 1]);
    ull bB = pack2(bp[c + 2], bp[c + 3]);
#pragma unroll
    for (int n = 0; n < 8; n++) { accA[n] = bA; accB[n] = bB; }
}

template<int OPAD>
__device__ __forceinline__ void store_acc(float* __restrict__ out, int n0, int off,
                                          const ull* accA, const ull* accB)
{
#pragma unroll
    for (int n = 0; n < 8; n++) {
        float2 a = unpack2(accA[n]), b = unpack2(accB[n]);
        *(float4*)(out + (n0 + n)*OPAD + off) = make_float4(a.x, a.y, b.x, b.y);
    }
}

__global__ void __launch_bounds__(THREADS, 1)
gnn_fused_kernel(const float* __restrict__ x,
                 const float* __restrict__ enc_W, const float* __restrict__ enc_b,
                 const float* __restrict__ Wq, const float* __restrict__ bq,
                 const float* __restrict__ Wk, const float* __restrict__ bk,
                 const float* __restrict__ Wv, const float* __restrict__ bv,
                 const float* __restrict__ ln_g, const float* __restrict__ ln_b,
                 const float* __restrict__ W1, const float* __restrict__ b1,
                 const float* __restrict__ W2, const float* __restrict__ b2,
                 float* __restrict__ out)
{
    extern __shared__ float sm[];
    const unsigned smb = su32(sm);
    float* bias = sm + OFF_BIAS;

    const int tid  = threadIdx.x;
    const int lane = tid & 31;
    const int warp = tid >> 5;
    const int gs   = warp >> 1;
    const int wsub = warp & 1;
    const int n0   = wsub * 8;
    const int c    = lane << 2;                       // my 4 output columns
    const int qoff = (c >> 5)*36 + (c & 31);          // head-padded offset

    float* hg = sm + OFF_DATA + gs*GFL;
    float* qg = hg + 16*HPAD;          // +2112
    float* kg = qg + 16*QPAD;          // +2304
    float* vg = kg + 16*QPAD;

    // ---- mbarriers + first two weight chunks ----
    if (tid == 0) {
        mbar_init(smb + MBAR_B,     1);
        mbar_init(smb + MBAR_B + 8, 1);
        asm volatile("fence.proxy.async.shared::cta;" ::: "memory");
        bulk_issue(smb + OFF_WB0*4, enc_W, 32768u, smb + MBAR_B);       // c0
        bulk_issue(smb + OFF_WB1*4, Wq,    32768u, smb + MBAR_B + 8);   // c1
    }

    // ---- preload biases / ln params ----
    for (int i = tid; i < 128; i += THREADS) {
        bias[B_ENC + i] = enc_b[i];
        bias[B_B1  + i] = b1[i];
    }
    for (int i = tid; i < 256; i += THREADS) {
        bias[B_BQ  + i] = bq[i];
        bias[B_BK  + i] = bk[i];
        bias[B_BV  + i] = bv[i];
        bias[B_LNG + i] = ln_g[i];
        bias[B_LNB + i] = ln_b[i];
    }
    if (tid < NC) bias[B_B2 + tid] = b2[tid];

    // ---- stage x (4 graphs x 1024 floats) into Q region, row stride 64 ----
    {
        const float4* xs = (const float4*)(x + (size_t)blockIdx.x * (G*NNODES*NDIM));
        float* xb = sm + OFF_DATA + 16*HPAD;     // qg of graph 0
        for (int i = tid; i < (G*NNODES*NDIM)/4; i += THREADS) {
            int g = i >> 8;              // 256 float4 per graph
            int r = i & 255;
            *(float4*)(xb + g*GFL + (r << 2)) = xs[i];
        }
    }
    __syncthreads();    // publish biases + x staging + mbarrier init

    int wc = 0;         // next chunk to consume
    int ic = 2;         // next chunk to issue
#define TWAIT() mbw(smb + MBAR_B + (wc & 1)*8, (wc >> 1) & 1)
#define TISSUE(src, bytes) do { if (tid == 0) \
        bulk_issue(smb + ((ic & 1) ? OFF_WB1 : OFF_WB0)*4, (src), (bytes), \
                   smb + MBAR_B + (ic & 1)*8); ic++; } while (0)

    ull accA[8], accB[8];

    // ---- encode: h = x @ enc_W + enc_b  (K=64, one chunk) ----
    {
        TWAIT();                               // c0
        acc_init(accA, accB, bias + B_ENC, c);
        gemm64<NDIM>(qg + n0*NDIM, sm + OFF_WB0, c, accA, accB);
        store_acc<HPAD>(hg, n0, c, accA, accB);
        __syncthreads();
        TISSUE(Wq + 8192, 32768u);             // c2: Wq[0] rows 64..127
        wc = 1;
    }

    const float scale = 0.1767766952966369f;   // 1/sqrt(32)

    for (int l = 0; l < 2; l++) {
        const float* nexts[6] = {
            Wk + l*16384, Wk + l*16384 + 8192,
            Wv + l*16384, Wv + l*16384 + 8192,
            (l == 0) ? (Wq + 16384) : W1,
            (l == 0) ? (Wq + 16384 + 8192) : (W1 + 8192)
        };
        const float* bptr[3] = { bias + B_BQ + 128*l, bias + B_BK + 128*l,
                                 bias + B_BV + 128*l };
        float* outs[3] = { qg, kg, vg };

#pragma unroll
        for (int s = 0; s < 3; s++) {
            TWAIT();
            acc_init(accA, accB, bptr[s], c);
            gemm64<HPAD>(hg + n0*HPAD, sm + ((wc & 1) ? OFF_WB1 : OFF_WB0), c, accA, accB);
            __syncthreads();
            TISSUE(nexts[2*s], 32768u);
            wc++;
            TWAIT();
            gemm64<HPAD>(hg + n0*HPAD + 64, sm + ((wc & 1) ? OFF_WB1 : OFF_WB0), c, accA, accB);
            store_acc<QPAD>(outs[s], n0, qoff, accA, accB);
            __syncthreads();
            TISSUE(nexts[2*s + 1], 32768u);
            wc++;
        }

        // ---- attention + residual + layernorm (registers; lane=(node,head)) ----
        {
            const int n  = n0 + (lane & 7);
            const int hh = lane >> 3;
            const int co = hh * 36;      // q/k/v head-padded offset
            const int ch = hh * 32;      // hg linear offset

            float q[32];
            const float* qr = qg + n*QPAD + co;
#pragma unroll
            for (int j = 0; j < 8; j++) {
                float4 t = *(const float4*)(qr + 4*j);
                q[4*j] = t.x; q[4*j+1] = t.y; q[4*j+2] = t.z; q[4*j+3] = t.w;
            }
            float s[16];
#pragma unroll
            for (int m = 0; m < 16; m++) {
                const float* kr = kg + m*QPAD + co;
                float a0 = 0.f, a1 = 0.f, a2 = 0.f, a3 = 0.f;
#pragma unroll
                for (int j = 0; j < 8; j++) {
                    float4 t = *(const float4*)(kr + 4*j);
                    a0 += q[4*j]  *t.x; a1 += q[4*j+1]*t.y;
                    a2 += q[4*j+2]*t.z; a3 += q[4*j+3]*t.w;
                }
                s[m] = (a0 + a1 + a2 + a3) * scale;
            }
            float mx = s[0];
#pragma unroll
            for (int m = 1; m < 16; m++) mx = fmaxf(mx, s[m]);
            float ssum = 0.f;
#pragma unroll
            for (int m = 0; m < 16; m++) { s[m] = __expf(s[m] - mx); ssum += s[m]; }
            float inv = 1.f / ssum;

            float o[32];
#pragma unroll
            for (int j = 0; j < 32; j++) o[j] = 0.f;
#pragma unroll
            for (int m = 0; m < 16; m++) {
                float p = s[m] * inv;
                const float* vr = vg + m*QPAD + co;
#pragma unroll
                for (int j = 0; j < 8; j++) {
                    float4 t = *(const float4*)(vr + 4*j);
                    o[4*j]   += p*t.x; o[4*j+1] += p*t.y;
                    o[4*j+2] += p*t.z; o[4*j+3] += p*t.w;
                }
            }
            // residual
            float* hr = hg + n*HPAD + ch;
#pragma unroll
            for (int j = 0; j < 8; j++) {
                float4 t = *(const float4*)(hr + 4*j);
                o[4*j] += t.x; o[4*j+1] += t.y; o[4*j+2] += t.z; o[4*j+3] += t.w;
            }
            // LN stats across the 4 head-lanes of this node
            float lsum = 0.f, lsq = 0.f;
#pragma unroll
            for (int j = 0; j < 32; j++) { lsum += o[j]; lsq += o[j]*o[j]; }
            lsum += __shfl_xor_sync(0xffffffffu, lsum, 8);
            lsq  += __shfl_xor_sync(0xffffffffu, lsq,  8);
            lsum += __shfl_xor_sync(0xffffffffu, lsum, 16);
            lsq  += __shfl_xor_sync(0xffffffffu, lsq,  16);
            float mean = lsum * (1.f/HID);
            float var  = lsq  * (1.f/HID) - mean*mean;
            float rstd = rsqrtf(var + 1e-5f);
#pragma unroll
            for (int j = 0; j < 32; j++)
                o[j] = (o[j] - mean) * rstd * bias[B_LNG + 128*l + ch + j]
                       + bias[B_LNB + 128*l + ch + j];
#pragma unroll
            for (int j = 0; j < 8; j++)
                *(float4*)(hr + 4*j) = make_float4(o[4*j], o[4*j+1], o[4*j+2], o[4*j+3]);
        }
        __syncthreads();
    }

    // ---- pooling into qg scratch: [0..128)=mean, [128..256)=max ----
    {
        int cA = wsub*64 + lane, cB = cA + 32;
        float sA = 0.f, sB = 0.f, mA = -3.4e38f, mB = -3.4e38f;
#pragma unroll
        for (int nn = 0; nn < 16; nn++) {
            float a = hg[nn*HPAD + cA]; sA += a; mA = fmaxf(mA, a);
            float b = hg[nn*HPAD + cB]; sB += b; mB = fmaxf(mB, b);
        }
        qg[cA]       = sA * (1.f/16.f);
        qg[HID + cA] = mA;
        qg[cB]       = sB * (1.f/16.f);
        qg[HID + cB] = mB;
    }
    __syncthreads();

    // ---- MLP layer 1: 4 chunks of W1 (256x128); c13,c14 already in flight ----
    {
        int cA = wsub*64 + lane, cB = cA + 32;
        float a1 = bias[B_B1 + cA];
        float a2 = bias[B_B1 + cB];
        for (int cc = 0; cc < 4; cc++) {
            TWAIT();
            float* bufp = sm + ((wc & 1) ? OFF_WB1 : OFF_WB0);
#pragma unroll 8
            for (int k = 0; k < 64; k++) {
                float pv = qg[64*cc + k];
                a1 = fmaf(pv, bufp[k*HID + cA], a1);
                a2 = fmaf(pv, bufp[k*HID + cB], a2);
            }
            __syncthreads();
            if (cc < 3) {
                const float* src = (cc < 2) ? (W1 + (cc + 2)*8192) : W2;
                unsigned nb = (cc < 2) ? 32768u : 5120u;   // W2 = 128*10 fl = 5120 B
                TISSUE(src, nb);
            }
            wc++;
        }
        kg[cA] = fmaxf(a1, 0.f);
        kg[cB] = fmaxf(a2, 0.f);
    }
    __syncthreads();

    // ---- logits = hid @ W2 + b2 ----
    TWAIT();    // c17
    {
        const float* Wc = sm + ((wc & 1) ? OFF_WB1 : OFF_WB0);
        if (wsub == 0 && lane < NC) {
            float a = bias[B_B2 + lane];
#pragma unroll 8
            for (int k = 0; k < HID; k++)
                a = fmaf(kg[k], Wc[k*NC + lane], a);
            out[((size_t)blockIdx.x*G + gs)*NC + lane] = a;
        }
    }
#undef TWAIT
#undef TISSUE
}

extern "C" void kernel_launch(void* const* d_in, const int* in_sizes, int n_in,
                              void* d_out, int out_size)
{
    const float* x     = (const float*)d_in[0];
    const float* enc_W = (const float*)d_in[1];
    const float* enc_b = (const float*)d_in[2];
    const float* Wq    = (const float*)d_in[3];
    const float* bq    = (const float*)d_in[4];
    const float* Wk    = (const float*)d_in[5];
    const float* bk    = (const float*)d_in[6];
    const float* Wv    = (const float*)d_in[7];
    const float* bv    = (const float*)d_in[8];
    const float* ln_g  = (const float*)d_in[9];
    const float* ln_b  = (const float*)d_in[10];
    const float* W1    = (const float*)d_in[11];
    const float* b1    = (const float*)d_in[12];
    const float* W2    = (const float*)d_in[13];
    const float* b2    = (const float*)d_in[14];
    float* out = (float*)d_out;

    cudaFuncSetAttribute(gnn_fused_kernel,
                         cudaFuncAttributeMaxDynamicSharedMemorySize, SMEM_BYTES);

    gnn_fused_kernel<<<B_TOTAL / G, THREADS, SMEM_BYTES>>>(
        x, enc_W, enc_b, Wq, bq, Wk, bk, Wv, bv, ln_g, ln_b, W1, b1, W2, b2, out);
}